// round 7
// baseline (speedup 1.0000x reference)
#include <cuda_runtime.h>
#include <cuda_fp16.h>
#include <math.h>

#define DD 64
#define NMAX 50000
#define EMAX 800000
#define INV_SQRT2 0.70710678118654752440f

typedef unsigned long long u64;

// ---- scratch (device globals: allocation-free) ----
__device__ __half g_embh[(size_t)EMAX * DD]; // bond output fp16, DST-SORTED edge order
__device__ float g_agg[(size_t)NMAX * DD];   // scatter-add target
__device__ float g_h[(size_t)NMAX * DD];     // MLP output (pre-BN)
__device__ float g_xa[(size_t)NMAX * DD];    // x ping
__device__ float g_xb[(size_t)NMAX * DD];    // x pong
__device__ float g_bsum[3][DD];              // BN sum per layer/feature
__device__ float g_bsq[3][DD];               // BN sumsq per layer/feature
// sort scratch
__device__ int g_cur[NMAX];                  // counts / cursors
__device__ int g_off[NMAX + 1];              // CSR offsets (scan of counts)
__device__ int g_srcs[EMAX];                 // src id in sorted order
__device__ int g_dstp[EMAX];                 // dst id in sorted order
__device__ int g_pos[EMAX];                  // sorted position of original edge e

// ---- packed f32x2 helpers ----
__device__ __forceinline__ u64 pack2(float lo, float hi) {
    u64 r; asm("mov.b64 %0, {%1, %2};" : "=l"(r) : "f"(lo), "f"(hi)); return r;
}
__device__ __forceinline__ void ffma2(u64& acc, u64 a, u64 b) {
    asm("fma.rn.f32x2 %0, %1, %2, %0;" : "+l"(acc) : "l"(a), "l"(b));
}
__device__ __forceinline__ float unpack_sum(u64 v) {
    float lo, hi; asm("mov.b64 {%0, %1}, %2;" : "=f"(lo), "=f"(hi) : "l"(v));
    return lo + hi;
}
__device__ __forceinline__ float unpack_sum2(u64 a, u64 b) {
    float alo, ahi, blo, bhi;
    asm("mov.b64 {%0, %1}, %2;" : "=f"(alo), "=f"(ahi) : "l"(a));
    asm("mov.b64 {%0, %1}, %2;" : "=f"(blo), "=f"(bhi) : "l"(b));
    return (alo + blo) + (ahi + bhi);
}

__device__ __forceinline__ float gelu_exact(float v) {
    return 0.5f * v * (1.0f + erff(v * 0.70710678118654752440f));
}

__device__ __forceinline__ const float* sel_in(int s, const float* ext) {
    return (s == 0) ? ext : ((s == 1) ? g_xa : g_xb);
}
__device__ __forceinline__ float* sel_out(int s, float* ext) {
    return (s == 0) ? ext : ((s == 1) ? g_xa : g_xb);
}

// ============================================================
// Sort phase: counting sort of edges by dst
// ============================================================
__global__ void k_cnt0(int N)
{
    int i = blockIdx.x * blockDim.x + threadIdx.x;
    if (i < N) g_cur[i] = 0;
    if (i < 3 * DD) { ((float*)g_bsum)[i] = 0.f; ((float*)g_bsq)[i] = 0.f; }
    if (i < N * 16) ((float4*)g_agg)[i] = make_float4(0.f, 0.f, 0.f, 0.f);
}

__global__ void k_count(const int* __restrict__ dst, int E)
{
    int e = blockIdx.x * blockDim.x + threadIdx.x;
    if (e < E) atomicAdd(&g_cur[dst[e]], 1);
}

__global__ void __launch_bounds__(1024) k_scan(int N)
{
    __shared__ int ssum[1024];
    int t = threadIdx.x;
    int C = (N + 1023) >> 10;
    int beg = t * C;
    int end = min(beg + C, N);
    int s = 0;
    for (int i = beg; i < end; i++) s += g_cur[i];
    ssum[t] = s;
    __syncthreads();
    for (int off = 1; off < 1024; off <<= 1) {
        int v = (t >= off) ? ssum[t - off] : 0;
        __syncthreads();
        ssum[t] += v;
        __syncthreads();
    }
    int run = (t == 0) ? 0 : ssum[t - 1];
    for (int i = beg; i < end; i++) {
        int c = g_cur[i];
        g_off[i] = run;
        run += c;
        g_cur[i] = 0;
    }
    if (beg < N && end == N) g_off[N] = run;
}

__global__ void k_scatter(const int* __restrict__ src,
                          const int* __restrict__ dst, int E)
{
    int e = blockIdx.x * blockDim.x + threadIdx.x;
    if (e >= E) return;
    int t = dst[e];
    int r = atomicAdd(&g_cur[t], 1);
    int p = g_off[t] + r;
    g_pos[e]  = p;
    g_srcs[p] = src[e];
    g_dstp[p] = t;
}

// ============================================================
// K_bond: emb = attr @ W_be + b_be -> fp16, written in sorted order.
// 256 thr = 4 rows x 64 dims, packed f32x2, split accumulators.
// ============================================================
__global__ void __launch_bounds__(256) k_bond(
    const float* __restrict__ attr,
    const float* __restrict__ Wbe,
    const float* __restrict__ bbe, int E)
{
    int r = threadIdx.x >> 6;
    int d = threadIdx.x & 63;

    u64 wp[32];
#pragma unroll
    for (int j = 0; j < 32; j++)
        wp[j] = pack2(Wbe[(2 * j) * DD + d], Wbe[(2 * j + 1) * DD + d]);
    float bias = bbe[d];

    for (int base = blockIdx.x * 4; base < E; base += gridDim.x * 4) {
        int row = base + r;
        if (row >= E) continue;
        const ulonglong2* a2 = (const ulonglong2*)(attr + (size_t)row * DD);
        u64 acca = 0, accb = 0;
#pragma unroll
        for (int k4 = 0; k4 < 8; k4++) {
            ulonglong2 a = a2[k4];
            ffma2(acca, a.x, wp[2 * k4]);
            ffma2(acca, a.y, wp[2 * k4 + 1]);
            ulonglong2 b = a2[k4 + 8];
            ffma2(accb, b.x, wp[2 * k4 + 16]);
            ffma2(accb, b.y, wp[2 * k4 + 17]);
        }
        g_embh[(size_t)__ldg(&g_pos[row]) * DD + d] =
            __float2half_rn(unpack_sum2(acca, accb) + bias);
    }
}

// ============================================================
// K_msg: over SORTED edges. Warp = 32 consecutive edges, fixed
// 8-dim group q (= warp id). Segmented suffix-sum by dst via shfl,
// run leaders issue the (rare) vector atomics.
// ============================================================
__global__ void __launch_bounds__(256) k_msg(
    int xsel, const float* __restrict__ xext, int E)
{
    int lane = threadIdx.x & 31;
    int q    = threadIdx.x >> 5;          // 0..7: dims [8q, 8q+8)
    int p    = blockIdx.x * 32 + lane;    // sorted edge index
    const float* x = sel_in(xsel, xext);

    int t = -1;
    float m[8];
#pragma unroll
    for (int j = 0; j < 8; j++) m[j] = 0.f;

    if (p < E) {
        int s = g_srcs[p];
        t     = g_dstp[p];
        uint4 eh = ((const uint4*)g_embh)[(size_t)p * 8 + q];
        float2 e0 = __half22float2(*(__half2*)&eh.x);
        float2 e1 = __half22float2(*(__half2*)&eh.y);
        float2 e2 = __half22float2(*(__half2*)&eh.z);
        float2 e3 = __half22float2(*(__half2*)&eh.w);
        float4 x0 = ((const float4*)x)[(size_t)s * 16 + q * 2];
        float4 x1 = ((const float4*)x)[(size_t)s * 16 + q * 2 + 1];
        m[0] = gelu_exact(e0.x + x0.x);
        m[1] = gelu_exact(e0.y + x0.y);
        m[2] = gelu_exact(e1.x + x0.z);
        m[3] = gelu_exact(e1.y + x0.w);
        m[4] = gelu_exact(e2.x + x1.x);
        m[5] = gelu_exact(e2.y + x1.y);
        m[6] = gelu_exact(e3.x + x1.z);
        m[7] = gelu_exact(e3.y + x1.w);
    }

    // leader = first lane of a dst-run within this warp
    int tprev = __shfl_up_sync(0xffffffffu, t, 1);
    bool leader = (lane == 0) || (tprev != t);

    // segmented suffix sum over contiguous equal-dst runs
#pragma unroll
    for (int sft = 1; sft < 32; sft <<= 1) {
        int tn = __shfl_down_sync(0xffffffffu, t, sft);
        float mn[8];
#pragma unroll
        for (int j = 0; j < 8; j++) mn[j] = __shfl_down_sync(0xffffffffu, m[j], sft);
        bool ok = (lane + sft < 32) && (tn == t);
        if (ok) {
#pragma unroll
            for (int j = 0; j < 8; j++) m[j] += mn[j];
        }
    }

    if (leader && p < E) {
        float4* pa = ((float4*)g_agg) + (size_t)t * 16 + q * 2;
        float4 v0 = make_float4(m[0], m[1], m[2], m[3]);
        float4 v1 = make_float4(m[4], m[5], m[6], m[7]);
#if defined(__CUDA_ARCH__) && (__CUDA_ARCH__ >= 900)
        atomicAdd(pa,     v0);
        atomicAdd(pa + 1, v1);
#else
        float* pf = (float*)pa;
        atomicAdd(pf + 0, v0.x); atomicAdd(pf + 1, v0.y);
        atomicAdd(pf + 2, v0.z); atomicAdd(pf + 3, v0.w);
        atomicAdd(pf + 4, v1.x); atomicAdd(pf + 5, v1.y);
        atomicAdd(pf + 6, v1.z); atomicAdd(pf + 7, v1.w);
#endif
    }
}

// ============================================================
// K_mlp: h = gelu(((1+eps)x + agg) @ W1 + b1) @ W2 + b2 ; BN stats.
// 64 threads (thread owns dim d), 4 rows/iter, f32x2, split accumulators.
// ============================================================
__global__ void __launch_bounds__(64) k_mlp(
    int xsel, const float* __restrict__ xext,
    const float* __restrict__ W1, const float* __restrict__ b1,
    const float* __restrict__ W2, const float* __restrict__ b2,
    const float* __restrict__ epsp, int layer, int N)
{
    __shared__ __align__(16) float s_in[4][DD];
    __shared__ __align__(16) float s_h1[4][DD];

    const float* x = sel_in(xsel, xext);
    int d = threadIdx.x;

    u64 w1p[32], w2p[32];
#pragma unroll
    for (int j = 0; j < 32; j++) {
        w1p[j] = pack2(W1[(2 * j) * DD + d], W1[(2 * j + 1) * DD + d]);
        w2p[j] = pack2(W2[(2 * j) * DD + d], W2[(2 * j + 1) * DD + d]);
    }
    float bb1 = b1[d], bb2 = b2[d];
    float eps1 = 1.0f + epsp[layer];

    float lsum = 0.f, lsq = 0.f;

    for (int base = blockIdx.x * 4; base < N; base += gridDim.x * 4) {
        int nr = min(4, N - base);
#pragma unroll
        for (int r = 0; r < 4; r++)
            if (r < nr)
                s_in[r][d] = fmaf(eps1, x[(size_t)(base + r) * DD + d],
                                  g_agg[(size_t)(base + r) * DD + d]);
        __syncthreads();

        {
            const ulonglong2* r0 = (const ulonglong2*)s_in[0];
            const ulonglong2* r1 = (const ulonglong2*)s_in[1];
            const ulonglong2* r2 = (const ulonglong2*)s_in[2];
            const ulonglong2* r3 = (const ulonglong2*)s_in[3];
            u64 A0a = 0, A1a = 0, A2a = 0, A3a = 0;
            u64 A0b = 0, A1b = 0, A2b = 0, A3b = 0;
#pragma unroll
            for (int k4 = 0; k4 < 8; k4++) {
                ulonglong2 v0 = r0[k4], v1 = r1[k4], v2 = r2[k4], v3 = r3[k4];
                ffma2(A0a, v0.x, w1p[2*k4]); ffma2(A0a, v0.y, w1p[2*k4+1]);
                ffma2(A1a, v1.x, w1p[2*k4]); ffma2(A1a, v1.y, w1p[2*k4+1]);
                ffma2(A2a, v2.x, w1p[2*k4]); ffma2(A2a, v2.y, w1p[2*k4+1]);
                ffma2(A3a, v3.x, w1p[2*k4]); ffma2(A3a, v3.y, w1p[2*k4+1]);
                ulonglong2 u0 = r0[k4+8], u1 = r1[k4+8], u2 = r2[k4+8], u3 = r3[k4+8];
                ffma2(A0b, u0.x, w1p[2*k4+16]); ffma2(A0b, u0.y, w1p[2*k4+17]);
                ffma2(A1b, u1.x, w1p[2*k4+16]); ffma2(A1b, u1.y, w1p[2*k4+17]);
                ffma2(A2b, u2.x, w1p[2*k4+16]); ffma2(A2b, u2.y, w1p[2*k4+17]);
                ffma2(A3b, u3.x, w1p[2*k4+16]); ffma2(A3b, u3.y, w1p[2*k4+17]);
            }
            s_h1[0][d] = gelu_exact(unpack_sum2(A0a, A0b) + bb1);
            s_h1[1][d] = gelu_exact(unpack_sum2(A1a, A1b) + bb1);
            s_h1[2][d] = gelu_exact(unpack_sum2(A2a, A2b) + bb1);
            s_h1[3][d] = gelu_exact(unpack_sum2(A3a, A3b) + bb1);
        }
        __syncthreads();

        {
            const ulonglong2* r0 = (const ulonglong2*)s_h1[0];
            const ulonglong2* r1 = (const ulonglong2*)s_h1[1];
            const ulonglong2* r2 = (const ulonglong2*)s_h1[2];
            const ulonglong2* r3 = (const ulonglong2*)s_h1[3];
            u64 C0a = 0, C1a = 0, C2a = 0, C3a = 0;
            u64 C0b = 0, C1b = 0, C2b = 0, C3b = 0;
#pragma unroll
            for (int k4 = 0; k4 < 8; k4++) {
                ulonglong2 v0 = r0[k4], v1 = r1[k4], v2 = r2[k4], v3 = r3[k4];
                ffma2(C0a, v0.x, w2p[2*k4]); ffma2(C0a, v0.y, w2p[2*k4+1]);
                ffma2(C1a, v1.x, w2p[2*k4]); ffma2(C1a, v1.y, w2p[2*k4+1]);
                ffma2(C2a, v2.x, w2p[2*k4]); ffma2(C2a, v2.y, w2p[2*k4+1]);
                ffma2(C3a, v3.x, w2p[2*k4]); ffma2(C3a, v3.y, w2p[2*k4+1]);
                ulonglong2 u0 = r0[k4+8], u1 = r1[k4+8], u2 = r2[k4+8], u3 = r3[k4+8];
                ffma2(C0b, u0.x, w2p[2*k4+16]); ffma2(C0b, u0.y, w2p[2*k4+17]);
                ffma2(C1b, u1.x, w2p[2*k4+16]); ffma2(C1b, u1.y, w2p[2*k4+17]);
                ffma2(C2b, u2.x, w2p[2*k4+16]); ffma2(C2b, u2.y, w2p[2*k4+17]);
                ffma2(C3b, u3.x, w2p[2*k4+16]); ffma2(C3b, u3.y, w2p[2*k4+17]);
            }
            float cc[4];
            cc[0] = unpack_sum2(C0a, C0b) + bb2;
            cc[1] = unpack_sum2(C1a, C1b) + bb2;
            cc[2] = unpack_sum2(C2a, C2b) + bb2;
            cc[3] = unpack_sum2(C3a, C3b) + bb2;
#pragma unroll
            for (int r = 0; r < 4; r++) {
                if (r < nr) {
                    g_h[(size_t)(base + r) * DD + d] = cc[r];
                    lsum += cc[r];
                    lsq = fmaf(cc[r], cc[r], lsq);
                }
            }
        }
        __syncthreads();
    }
    atomicAdd(&g_bsum[layer][d], lsum);
    atomicAdd(&g_bsq[layer][d],  lsq);
}

// ============================================================
// K_bn: x_next = (x + gelu(BN(h))) * INV_SQRT2 ; zero agg for next layer
// ============================================================
__global__ void k_bn(int xsel, const float* __restrict__ xext,
                     int osel, float* __restrict__ oext,
                     const float* __restrict__ gamma,
                     const float* __restrict__ beta, int layer, int N)
{
    int idx = blockIdx.x * blockDim.x + threadIdx.x;
    if (idx >= N * 16) return;
    const float* xin = sel_in(xsel, xext);
    float* xout = sel_out(osel, oext);

    int q = idx & 15;
    float invN = 1.0f / (float)N;
    float4 hv = ((const float4*)g_h)[idx];
    float4 xv = ((const float4*)xin)[idx];
    float hvv[4] = {hv.x, hv.y, hv.z, hv.w};
    float xvv[4] = {xv.x, xv.y, xv.z, xv.w};
    float o[4];
#pragma unroll
    for (int j = 0; j < 4; j++) {
        int dd = q * 4 + j;
        float mu   = g_bsum[layer][dd] * invN;
        float var  = g_bsq[layer][dd] * invN - mu * mu;
        float rstd = rsqrtf(var + 1e-5f);
        float hn   = (hvv[j] - mu) * rstd * gamma[dd] + beta[dd];
        o[j] = (xvv[j] + gelu_exact(hn)) * INV_SQRT2;
    }
    ((float4*)xout)[idx] = make_float4(o[0], o[1], o[2], o[3]);
    ((float4*)g_agg)[idx] = make_float4(0.f, 0.f, 0.f, 0.f);
}

// ============================================================
// launcher
// ============================================================
extern "C" void kernel_launch(void* const* d_in, const int* in_sizes, int n_in,
                              void* d_out, int out_size)
{
    const float* x0    = (const float*)d_in[0];
    const int*   eidx  = (const int*)  d_in[1];
    const float* eattr = (const float*)d_in[2];
    const float* Wbe   = (const float*)d_in[3];
    const float* bbe   = (const float*)d_in[4];
    const float* epsp  = (const float*)d_in[5];
    const float* W1    = (const float*)d_in[6];
    const float* b1    = (const float*)d_in[7];
    const float* W2    = (const float*)d_in[8];
    const float* b2    = (const float*)d_in[9];
    const float* gamma = (const float*)d_in[10];
    const float* beta  = (const float*)d_in[11];

    int N = in_sizes[0] / DD;
    int E = in_sizes[1] / 2;
    const int* src = eidx;
    const int* dst = eidx + E;

    // sort edges by dst (once); also zeroes agg + BN stats
    k_cnt0   <<<(N * 16 + 255) / 256, 256>>>(N);
    k_count  <<<(E + 255) / 256, 256>>>(dst, E);
    k_scan   <<<1, 1024>>>(N);
    k_scatter<<<(E + 255) / 256, 256>>>(src, dst, E);

    // bond encoder once (fp16, sorted order)
    k_bond<<<4736, 256>>>(eattr, Wbe, bbe, E);

    // x schedule: L0: ext(x0)->g_xa ; L1: g_xa->g_xb ; L2: g_xb->ext(d_out)
    int in_sel[3]  = {0, 1, 2};
    int out_sel[3] = {1, 2, 0};

    int nblk_node = (N * 16 + 255) / 256;
    int nblk_msg  = (E + 31) / 32;

    for (int l = 0; l < 3; l++) {
        const float* xext = (l == 0) ? x0 : nullptr;
        k_msg<<<nblk_msg, 256>>>(in_sel[l], xext, E);
        k_mlp<<<2048, 64>>>(in_sel[l], xext,
                            W1 + (size_t)l * DD * DD, b1 + (size_t)l * DD,
                            W2 + (size_t)l * DD * DD, b2 + (size_t)l * DD,
                            epsp, l, N);
        k_bn<<<nblk_node, 256>>>(in_sel[l], xext, out_sel[l], (float*)d_out,
                                 gamma + (size_t)l * DD, beta + (size_t)l * DD, l, N);
    }
}

// round 8
// speedup vs baseline: 2.4175x; 2.4175x over previous
#include <cuda_runtime.h>
#include <cuda_fp16.h>
#include <mma.h>
#include <math.h>

using namespace nvcuda;

#define DD 64
#define NMAX 50000
#define EMAX 800000
#define INV_SQRT2 0.70710678118654752440f

// ---- scratch (device globals: allocation-free) ----
__device__ __half g_embh[(size_t)EMAX * DD]; // bond output fp16, natural edge order
__device__ float g_agg[(size_t)NMAX * DD];   // scatter-add target
__device__ float g_h[(size_t)NMAX * DD];     // MLP output (pre-BN)
__device__ float g_xa[(size_t)NMAX * DD];    // x ping
__device__ float g_xb[(size_t)NMAX * DD];    // x pong
__device__ float g_bsum[3][DD];              // BN sum per layer/feature
__device__ float g_bsq[3][DD];               // BN sumsq per layer/feature

typedef unsigned long long u64;

// ---- packed f32x2 helpers (used in k_mlp) ----
__device__ __forceinline__ u64 pack2(float lo, float hi) {
    u64 r; asm("mov.b64 %0, {%1, %2};" : "=l"(r) : "f"(lo), "f"(hi)); return r;
}
__device__ __forceinline__ void ffma2(u64& acc, u64 a, u64 b) {
    asm("fma.rn.f32x2 %0, %1, %2, %0;" : "+l"(acc) : "l"(a), "l"(b));
}
__device__ __forceinline__ float unpack_sum2(u64 a, u64 b) {
    float alo, ahi, blo, bhi;
    asm("mov.b64 {%0, %1}, %2;" : "=f"(alo), "=f"(ahi) : "l"(a));
    asm("mov.b64 {%0, %1}, %2;" : "=f"(blo), "=f"(bhi) : "l"(b));
    return (alo + blo) + (ahi + bhi);
}

__device__ __forceinline__ float gelu_exact(float v) {
    return 0.5f * v * (1.0f + erff(v * 0.70710678118654752440f));
}

__device__ __forceinline__ const float* sel_in(int s, const float* ext) {
    return (s == 0) ? ext : ((s == 1) ? g_xa : g_xb);
}
__device__ __forceinline__ float* sel_out(int s, float* ext) {
    return (s == 0) ? ext : ((s == 1) ? g_xa : g_xb);
}

// ============================================================
// K_bond (wmma): emb = attr @ W_be + b_be -> fp16, natural order.
// 256 threads = 8 warps. Tile: 128 rows x 64 dims, K=64.
// A staged fp32->fp16 in smem; W converted once per block.
// Each warp: 16-row strip, 4 n-tiles x 4 k-steps of m16n16k16 HMMA.
// ============================================================
__global__ void __launch_bounds__(256) k_bond(
    const float* __restrict__ attr,
    const float* __restrict__ Wbe,
    const float* __restrict__ bbe, int E)
{
    __shared__ __half As[128][72];        // 18.4 KB
    __shared__ __half Ws[64][72];         // 9.2 KB
    __shared__ float  Cs[8][16][16];      // 8 KB per-warp n-tile staging

    int tid  = threadIdx.x;
    int warp = tid >> 5;
    int lane = tid & 31;

    // convert W once
    for (int i = tid; i < 64 * 64; i += 256) {
        Ws[i >> 6][i & 63] = __float2half_rn(Wbe[i]);
    }
    // preload bias for this lane's epilogue slots: d = n*16 + (lane&1)*8 + j
    float bias[4][8];
#pragma unroll
    for (int n = 0; n < 4; n++)
#pragma unroll
        for (int j = 0; j < 8; j++)
            bias[n][j] = bbe[n * 16 + (lane & 1) * 8 + j];
    __syncthreads();

    for (int base = blockIdx.x * 128; base < E; base += gridDim.x * 128) {
        // ---- stage A tile: 128 rows x 64 floats -> fp16 smem ----
        for (int i = tid; i < 128 * 16; i += 256) {
            int rr = i >> 4, c4 = i & 15;
            int row = base + rr;
            float4 v = (row < E) ? ((const float4*)attr)[(size_t)row * 16 + c4]
                                 : make_float4(0.f, 0.f, 0.f, 0.f);
            __half2* dsty = (__half2*)&As[rr][c4 * 4];
            dsty[0] = __floats2half2_rn(v.x, v.y);
            dsty[1] = __floats2half2_rn(v.z, v.w);
        }
        __syncthreads();

        // ---- compute: warp owns rows [warp*16, warp*16+16) ----
        wmma::fragment<wmma::accumulator, 16, 16, 16, float> acc[4];
#pragma unroll
        for (int n = 0; n < 4; n++) wmma::fill_fragment(acc[n], 0.0f);

#pragma unroll
        for (int k = 0; k < 4; k++) {
            wmma::fragment<wmma::matrix_a, 16, 16, 16, __half, wmma::row_major> af;
            wmma::load_matrix_sync(af, &As[warp * 16][k * 16], 72);
#pragma unroll
            for (int n = 0; n < 4; n++) {
                wmma::fragment<wmma::matrix_b, 16, 16, 16, __half, wmma::row_major> bf;
                wmma::load_matrix_sync(bf, &Ws[k * 16][n * 16], 72);
                wmma::mma_sync(acc[n], af, bf, acc[n]);
            }
        }

        // ---- epilogue: per n-tile through smem, bias + fp16 store ----
#pragma unroll
        for (int n = 0; n < 4; n++) {
            wmma::store_matrix_sync(&Cs[warp][0][0], acc[n], 16, wmma::mem_row_major);
            __syncwarp();
            int r_in = lane >> 1;                 // 0..15
            int hsel = lane & 1;                  // 0/1 -> 8-col half of n-tile
            int row  = base + warp * 16 + r_in;
            if (row < E) {
                const float* csrc = &Cs[warp][r_in][hsel * 8];
                __half tmp[8];
#pragma unroll
                for (int j = 0; j < 8; j++)
                    tmp[j] = __float2half_rn(csrc[j] + bias[n][j]);
                int d0 = n * 16 + hsel * 8;
                *(uint4*)(&g_embh[(size_t)row * DD + d0]) = *(uint4*)tmp;
            }
            __syncwarp();
        }
        __syncthreads();
    }
}

// ============================================================
// K_zero: zero agg + BN stats
// ============================================================
__global__ void k_zero(int N)
{
    int idx = blockIdx.x * blockDim.x + threadIdx.x;
    if (idx < N * 16) ((float4*)g_agg)[idx] = make_float4(0.f, 0.f, 0.f, 0.f);
    if (blockIdx.x == 0 && threadIdx.x < 3 * DD) {
        ((float*)g_bsum)[threadIdx.x] = 0.f;
        ((float*)g_bsq)[threadIdx.x]  = 0.f;
    }
}

// ============================================================
// K_msg: m = gelu(x[src] + emb); agg[dst] += m
// one thread per (edge, 8-dim group): 1 LDG.128 emb, 2 float4 x,
// 8 gelu, 2 vector atomics.  (R6-proven version)
// ============================================================
__global__ void k_msg(int xsel, const float* __restrict__ xext,
                      const int* __restrict__ src,
                      const int* __restrict__ dst, int E)
{
    int idx = blockIdx.x * blockDim.x + threadIdx.x;
    if (idx >= E * 8) return;
    const float* x = sel_in(xsel, xext);
    int e = idx >> 3, q = idx & 7;
    int s = src[e], t = dst[e];

    uint4 eh = ((const uint4*)g_embh)[(size_t)e * 8 + q];
    float2 e0 = __half22float2(*(__half2*)&eh.x);
    float2 e1 = __half22float2(*(__half2*)&eh.y);
    float2 e2 = __half22float2(*(__half2*)&eh.z);
    float2 e3 = __half22float2(*(__half2*)&eh.w);

    float4 x0 = ((const float4*)x)[(size_t)s * 16 + q * 2];
    float4 x1 = ((const float4*)x)[(size_t)s * 16 + q * 2 + 1];

    float4 m0, m1;
    m0.x = gelu_exact(e0.x + x0.x);
    m0.y = gelu_exact(e0.y + x0.y);
    m0.z = gelu_exact(e1.x + x0.z);
    m0.w = gelu_exact(e1.y + x0.w);
    m1.x = gelu_exact(e2.x + x1.x);
    m1.y = gelu_exact(e2.y + x1.y);
    m1.z = gelu_exact(e3.x + x1.z);
    m1.w = gelu_exact(e3.y + x1.w);

    float4* p = ((float4*)g_agg) + (size_t)t * 16 + q * 2;
#if defined(__CUDA_ARCH__) && (__CUDA_ARCH__ >= 900)
    atomicAdd(p,     m0);
    atomicAdd(p + 1, m1);
#else
    float* pf = (float*)p;
    atomicAdd(pf + 0, m0.x); atomicAdd(pf + 1, m0.y);
    atomicAdd(pf + 2, m0.z); atomicAdd(pf + 3, m0.w);
    atomicAdd(pf + 4, m1.x); atomicAdd(pf + 5, m1.y);
    atomicAdd(pf + 6, m1.z); atomicAdd(pf + 7, m1.w);
#endif
}

// ============================================================
// K_mlp: h = gelu(((1+eps)x + agg) @ W1 + b1) @ W2 + b2 ; BN stats.
// 64 threads (thread owns dim d), 4 rows/iter, f32x2, split accumulators.
// ============================================================
__global__ void __launch_bounds__(64) k_mlp(
    int xsel, const float* __restrict__ xext,
    const float* __restrict__ W1, const float* __restrict__ b1,
    const float* __restrict__ W2, const float* __restrict__ b2,
    const float* __restrict__ epsp, int layer, int N)
{
    __shared__ __align__(16) float s_in[4][DD];
    __shared__ __align__(16) float s_h1[4][DD];

    const float* x = sel_in(xsel, xext);
    int d = threadIdx.x;

    u64 w1p[32], w2p[32];
#pragma unroll
    for (int j = 0; j < 32; j++) {
        w1p[j] = pack2(W1[(2 * j) * DD + d], W1[(2 * j + 1) * DD + d]);
        w2p[j] = pack2(W2[(2 * j) * DD + d], W2[(2 * j + 1) * DD + d]);
    }
    float bb1 = b1[d], bb2 = b2[d];
    float eps1 = 1.0f + epsp[layer];

    float lsum = 0.f, lsq = 0.f;

    for (int base = blockIdx.x * 4; base < N; base += gridDim.x * 4) {
        int nr = min(4, N - base);
#pragma unroll
        for (int r = 0; r < 4; r++)
            if (r < nr)
                s_in[r][d] = fmaf(eps1, x[(size_t)(base + r) * DD + d],
                                  g_agg[(size_t)(base + r) * DD + d]);
        __syncthreads();

        {
            const ulonglong2* r0 = (const ulonglong2*)s_in[0];
            const ulonglong2* r1 = (const ulonglong2*)s_in[1];
            const ulonglong2* r2 = (const ulonglong2*)s_in[2];
            const ulonglong2* r3 = (const ulonglong2*)s_in[3];
            u64 A0a = 0, A1a = 0, A2a = 0, A3a = 0;
            u64 A0b = 0, A1b = 0, A2b = 0, A3b = 0;
#pragma unroll
            for (int k4 = 0; k4 < 8; k4++) {
                ulonglong2 v0 = r0[k4], v1 = r1[k4], v2 = r2[k4], v3 = r3[k4];
                ffma2(A0a, v0.x, w1p[2*k4]); ffma2(A0a, v0.y, w1p[2*k4+1]);
                ffma2(A1a, v1.x, w1p[2*k4]); ffma2(A1a, v1.y, w1p[2*k4+1]);
                ffma2(A2a, v2.x, w1p[2*k4]); ffma2(A2a, v2.y, w1p[2*k4+1]);
                ffma2(A3a, v3.x, w1p[2*k4]); ffma2(A3a, v3.y, w1p[2*k4+1]);
                ulonglong2 u0 = r0[k4+8], u1 = r1[k4+8], u2 = r2[k4+8], u3 = r3[k4+8];
                ffma2(A0b, u0.x, w1p[2*k4+16]); ffma2(A0b, u0.y, w1p[2*k4+17]);
                ffma2(A1b, u1.x, w1p[2*k4+16]); ffma2(A1b, u1.y, w1p[2*k4+17]);
                ffma2(A2b, u2.x, w1p[2*k4+16]); ffma2(A2b, u2.y, w1p[2*k4+17]);
                ffma2(A3b, u3.x, w1p[2*k4+16]); ffma2(A3b, u3.y, w1p[2*k4+17]);
            }
            s_h1[0][d] = gelu_exact(unpack_sum2(A0a, A0b) + bb1);
            s_h1[1][d] = gelu_exact(unpack_sum2(A1a, A1b) + bb1);
            s_h1[2][d] = gelu_exact(unpack_sum2(A2a, A2b) + bb1);
            s_h1[3][d] = gelu_exact(unpack_sum2(A3a, A3b) + bb1);
        }
        __syncthreads();

        {
            const ulonglong2* r0 = (const ulonglong2*)s_h1[0];
            const ulonglong2* r1 = (const ulonglong2*)s_h1[1];
            const ulonglong2* r2 = (const ulonglong2*)s_h1[2];
            const ulonglong2* r3 = (const ulonglong2*)s_h1[3];
            u64 C0a = 0, C1a = 0, C2a = 0, C3a = 0;
            u64 C0b = 0, C1b = 0, C2b = 0, C3b = 0;
#pragma unroll
            for (int k4 = 0; k4 < 8; k4++) {
                ulonglong2 v0 = r0[k4], v1 = r1[k4], v2 = r2[k4], v3 = r3[k4];
                ffma2(C0a, v0.x, w2p[2*k4]); ffma2(C0a, v0.y, w2p[2*k4+1]);
                ffma2(C1a, v1.x, w2p[2*k4]); ffma2(C1a, v1.y, w2p[2*k4+1]);
                ffma2(C2a, v2.x, w2p[2*k4]); ffma2(C2a, v2.y, w2p[2*k4+1]);
                ffma2(C3a, v3.x, w2p[2*k4]); ffma2(C3a, v3.y, w2p[2*k4+1]);
                ulonglong2 u0 = r0[k4+8], u1 = r1[k4+8], u2 = r2[k4+8], u3 = r3[k4+8];
                ffma2(C0b, u0.x, w2p[2*k4+16]); ffma2(C0b, u0.y, w2p[2*k4+17]);
                ffma2(C1b, u1.x, w2p[2*k4+16]); ffma2(C1b, u1.y, w2p[2*k4+17]);
                ffma2(C2b, u2.x, w2p[2*k4+16]); ffma2(C2b, u2.y, w2p[2*k4+17]);
                ffma2(C3b, u3.x, w2p[2*k4+16]); ffma2(C3b, u3.y, w2p[2*k4+17]);
            }
            float cc[4];
            cc[0] = unpack_sum2(C0a, C0b) + bb2;
            cc[1] = unpack_sum2(C1a, C1b) + bb2;
            cc[2] = unpack_sum2(C2a, C2b) + bb2;
            cc[3] = unpack_sum2(C3a, C3b) + bb2;
#pragma unroll
            for (int r = 0; r < 4; r++) {
                if (r < nr) {
                    g_h[(size_t)(base + r) * DD + d] = cc[r];
                    lsum += cc[r];
                    lsq = fmaf(cc[r], cc[r], lsq);
                }
            }
        }
        __syncthreads();
    }
    atomicAdd(&g_bsum[layer][d], lsum);
    atomicAdd(&g_bsq[layer][d],  lsq);
}

// ============================================================
// K_bn: x_next = (x + gelu(BN(h))) * INV_SQRT2 ; zero agg for next layer
// ============================================================
__global__ void k_bn(int xsel, const float* __restrict__ xext,
                     int osel, float* __restrict__ oext,
                     const float* __restrict__ gamma,
                     const float* __restrict__ beta, int layer, int N)
{
    int idx = blockIdx.x * blockDim.x + threadIdx.x;
    if (idx >= N * 16) return;
    const float* xin = sel_in(xsel, xext);
    float* xout = sel_out(osel, oext);

    int q = idx & 15;
    float invN = 1.0f / (float)N;
    float4 hv = ((const float4*)g_h)[idx];
    float4 xv = ((const float4*)xin)[idx];
    float hvv[4] = {hv.x, hv.y, hv.z, hv.w};
    float xvv[4] = {xv.x, xv.y, xv.z, xv.w};
    float o[4];
#pragma unroll
    for (int j = 0; j < 4; j++) {
        int dd = q * 4 + j;
        float mu   = g_bsum[layer][dd] * invN;
        float var  = g_bsq[layer][dd] * invN - mu * mu;
        float rstd = rsqrtf(var + 1e-5f);
        float hn   = (hvv[j] - mu) * rstd * gamma[dd] + beta[dd];
        o[j] = (xvv[j] + gelu_exact(hn)) * INV_SQRT2;
    }
    ((float4*)xout)[idx] = make_float4(o[0], o[1], o[2], o[3]);
    ((float4*)g_agg)[idx] = make_float4(0.f, 0.f, 0.f, 0.f);
}

// ============================================================
// launcher
// ============================================================
extern "C" void kernel_launch(void* const* d_in, const int* in_sizes, int n_in,
                              void* d_out, int out_size)
{
    const float* x0    = (const float*)d_in[0];
    const int*   eidx  = (const int*)  d_in[1];
    const float* eattr = (const float*)d_in[2];
    const float* Wbe   = (const float*)d_in[3];
    const float* bbe   = (const float*)d_in[4];
    const float* epsp  = (const float*)d_in[5];
    const float* W1    = (const float*)d_in[6];
    const float* b1    = (const float*)d_in[7];
    const float* W2    = (const float*)d_in[8];
    const float* b2    = (const float*)d_in[9];
    const float* gamma = (const float*)d_in[10];
    const float* beta  = (const float*)d_in[11];

    int N = in_sizes[0] / DD;
    int E = in_sizes[1] / 2;
    const int* src = eidx;
    const int* dst = eidx + E;

    // zero agg + BN stats (independent of bond)
    k_zero<<<(N * 16 + 255) / 256, 256>>>(N);
    // bond encoder once (wmma fp16, natural order): 6250 row-tiles of 128
    k_bond<<<(E + 127) / 128, 256>>>(eattr, Wbe, bbe, E);

    // x schedule: L0: ext(x0)->g_xa ; L1: g_xa->g_xb ; L2: g_xb->ext(d_out)
    int in_sel[3]  = {0, 1, 2};
    int out_sel[3] = {1, 2, 0};

    int nblk_node = (N * 16 + 255) / 256;
    int nblk_edge = (E * 8 + 255) / 256;

    for (int l = 0; l < 3; l++) {
        const float* xext = (l == 0) ? x0 : nullptr;
        k_msg<<<nblk_edge, 256>>>(in_sel[l], xext, src, dst, E);
        k_mlp<<<2048, 64>>>(in_sel[l], xext,
                            W1 + (size_t)l * DD * DD, b1 + (size_t)l * DD,
                            W2 + (size_t)l * DD * DD, b2 + (size_t)l * DD,
                            epsp, l, N);
        k_bn<<<nblk_node, 256>>>(in_sel[l], xext, out_sel[l], (float*)d_out,
                                 gamma + (size_t)l * DD, beta + (size_t)l * DD, l, N);
    }
}

// round 9
// speedup vs baseline: 2.6222x; 1.0847x over previous
#include <cuda_runtime.h>
#include <cuda_fp16.h>
#include <mma.h>
#include <math.h>

using namespace nvcuda;

#define DD 64
#define NMAX 50000
#define EMAX 800000
#define INV_SQRT2 0.70710678118654752440f

// ---- scratch (device globals: allocation-free) ----
__device__ __half g_embh[(size_t)EMAX * DD]; // bond output fp16, natural edge order
__device__ float g_agg[(size_t)NMAX * DD];   // scatter-add target
__device__ float g_h[(size_t)NMAX * DD];     // MLP output (pre-BN)
__device__ float g_xa[(size_t)NMAX * DD];    // x ping
__device__ float g_xb[(size_t)NMAX * DD];    // x pong
__device__ float g_bsum[3][DD];              // BN sum per layer/feature
__device__ float g_bsq[3][DD];               // BN sumsq per layer/feature

__device__ __forceinline__ float gelu_exact(float v) {
    return 0.5f * v * (1.0f + erff(v * 0.70710678118654752440f));
}

__device__ __forceinline__ const float* sel_in(int s, const float* ext) {
    return (s == 0) ? ext : ((s == 1) ? g_xa : g_xb);
}
__device__ __forceinline__ float* sel_out(int s, float* ext) {
    return (s == 0) ? ext : ((s == 1) ? g_xa : g_xb);
}

// ============================================================
// K_bond (wmma): emb = attr @ W_be + b_be -> fp16, natural order.
// (proven R8 version, unchanged)
// ============================================================
__global__ void __launch_bounds__(256) k_bond(
    const float* __restrict__ attr,
    const float* __restrict__ Wbe,
    const float* __restrict__ bbe, int E)
{
    __shared__ __half As[128][72];
    __shared__ __half Ws[64][72];
    __shared__ float  Cs[8][16][16];

    int tid  = threadIdx.x;
    int warp = tid >> 5;
    int lane = tid & 31;

    for (int i = tid; i < 64 * 64; i += 256)
        Ws[i >> 6][i & 63] = __float2half_rn(Wbe[i]);

    float bias[4][8];
#pragma unroll
    for (int n = 0; n < 4; n++)
#pragma unroll
        for (int j = 0; j < 8; j++)
            bias[n][j] = bbe[n * 16 + (lane & 1) * 8 + j];
    __syncthreads();

    for (int base = blockIdx.x * 128; base < E; base += gridDim.x * 128) {
        for (int i = tid; i < 128 * 16; i += 256) {
            int rr = i >> 4, c4 = i & 15;
            int row = base + rr;
            float4 v = (row < E) ? ((const float4*)attr)[(size_t)row * 16 + c4]
                                 : make_float4(0.f, 0.f, 0.f, 0.f);
            __half2* dsty = (__half2*)&As[rr][c4 * 4];
            dsty[0] = __floats2half2_rn(v.x, v.y);
            dsty[1] = __floats2half2_rn(v.z, v.w);
        }
        __syncthreads();

        wmma::fragment<wmma::accumulator, 16, 16, 16, float> acc[4];
#pragma unroll
        for (int n = 0; n < 4; n++) wmma::fill_fragment(acc[n], 0.0f);

#pragma unroll
        for (int k = 0; k < 4; k++) {
            wmma::fragment<wmma::matrix_a, 16, 16, 16, __half, wmma::row_major> af;
            wmma::load_matrix_sync(af, &As[warp * 16][k * 16], 72);
#pragma unroll
            for (int n = 0; n < 4; n++) {
                wmma::fragment<wmma::matrix_b, 16, 16, 16, __half, wmma::row_major> bf;
                wmma::load_matrix_sync(bf, &Ws[k * 16][n * 16], 72);
                wmma::mma_sync(acc[n], af, bf, acc[n]);
            }
        }

#pragma unroll
        for (int n = 0; n < 4; n++) {
            wmma::store_matrix_sync(&Cs[warp][0][0], acc[n], 16, wmma::mem_row_major);
            __syncwarp();
            int r_in = lane >> 1;
            int hsel = lane & 1;
            int row  = base + warp * 16 + r_in;
            if (row < E) {
                const float* csrc = &Cs[warp][r_in][hsel * 8];
                __half tmp[8];
#pragma unroll
                for (int j = 0; j < 8; j++)
                    tmp[j] = __float2half_rn(csrc[j] + bias[n][j]);
                int d0 = n * 16 + hsel * 8;
                *(uint4*)(&g_embh[(size_t)row * DD + d0]) = *(uint4*)tmp;
            }
            __syncwarp();
        }
        __syncthreads();
    }
}

// ============================================================
// K_zero: zero agg + BN stats
// ============================================================
__global__ void k_zero(int N)
{
    int idx = blockIdx.x * blockDim.x + threadIdx.x;
    if (idx < N * 16) ((float4*)g_agg)[idx] = make_float4(0.f, 0.f, 0.f, 0.f);
    if (blockIdx.x == 0 && threadIdx.x < 3 * DD) {
        ((float*)g_bsum)[threadIdx.x] = 0.f;
        ((float*)g_bsq)[threadIdx.x]  = 0.f;
    }
}

// ============================================================
// K_msg: m = gelu(x[src] + emb); agg[dst] += m  (R6-proven)
// ============================================================
__global__ void k_msg(int xsel, const float* __restrict__ xext,
                      const int* __restrict__ src,
                      const int* __restrict__ dst, int E)
{
    int idx = blockIdx.x * blockDim.x + threadIdx.x;
    if (idx >= E * 8) return;
    const float* x = sel_in(xsel, xext);
    int e = idx >> 3, q = idx & 7;
    int s = src[e], t = dst[e];

    uint4 eh = ((const uint4*)g_embh)[(size_t)e * 8 + q];
    float2 e0 = __half22float2(*(__half2*)&eh.x);
    float2 e1 = __half22float2(*(__half2*)&eh.y);
    float2 e2 = __half22float2(*(__half2*)&eh.z);
    float2 e3 = __half22float2(*(__half2*)&eh.w);

    float4 x0 = ((const float4*)x)[(size_t)s * 16 + q * 2];
    float4 x1 = ((const float4*)x)[(size_t)s * 16 + q * 2 + 1];

    float4 m0, m1;
    m0.x = gelu_exact(e0.x + x0.x);
    m0.y = gelu_exact(e0.y + x0.y);
    m0.z = gelu_exact(e1.x + x0.z);
    m0.w = gelu_exact(e1.y + x0.w);
    m1.x = gelu_exact(e2.x + x1.x);
    m1.y = gelu_exact(e2.y + x1.y);
    m1.z = gelu_exact(e3.x + x1.z);
    m1.w = gelu_exact(e3.y + x1.w);

    float4* p = ((float4*)g_agg) + (size_t)t * 16 + q * 2;
#if defined(__CUDA_ARCH__) && (__CUDA_ARCH__ >= 900)
    atomicAdd(p,     m0);
    atomicAdd(p + 1, m1);
#else
    float* pf = (float*)p;
    atomicAdd(pf + 0, m0.x); atomicAdd(pf + 1, m0.y);
    atomicAdd(pf + 2, m0.z); atomicAdd(pf + 3, m0.w);
    atomicAdd(pf + 4, m1.x); atomicAdd(pf + 5, m1.y);
    atomicAdd(pf + 6, m1.z); atomicAdd(pf + 7, m1.w);
#endif
}

// ============================================================
// K_mlp (wmma): h = gelu(((1+eps)x + agg) @ W1 + b1) @ W2 + b2
// 128-node tile, 8 warps. Input staged fp16; gelu(h1) written back
// into each warp's own A strip (per-warp isolation, no block sync
// between the two GEMMs). No BN stats here (see k_stat).
// ============================================================
__global__ void __launch_bounds__(256) k_mlp(
    int xsel, const float* __restrict__ xext,
    const float* __restrict__ W1, const float* __restrict__ b1,
    const float* __restrict__ W2, const float* __restrict__ b2,
    const float* __restrict__ epsp, int layer, int N)
{
    __shared__ __half As[128][72];
    __shared__ __half W1s[64][72];
    __shared__ __half W2s[64][72];
    __shared__ float  Cs[8][16][16];

    int tid  = threadIdx.x;
    int warp = tid >> 5;
    int lane = tid & 31;

    for (int i = tid; i < 64 * 64; i += 256) {
        W1s[i >> 6][i & 63] = __float2half_rn(W1[i]);
        W2s[i >> 6][i & 63] = __float2half_rn(W2[i]);
    }
    float bias1[4][8], bias2[4][8];
#pragma unroll
    for (int n = 0; n < 4; n++)
#pragma unroll
        for (int j = 0; j < 8; j++) {
            bias1[n][j] = b1[n * 16 + (lane & 1) * 8 + j];
            bias2[n][j] = b2[n * 16 + (lane & 1) * 8 + j];
        }
    float eps1 = 1.0f + epsp[layer];
    const float* x = sel_in(xsel, xext);
    __syncthreads();

    for (int base = blockIdx.x * 128; base < N; base += gridDim.x * 128) {
        // ---- stage input (1+eps)x + agg -> fp16 ----
        for (int i = tid; i < 128 * 16; i += 256) {
            int rr = i >> 4, c4 = i & 15;
            int row = base + rr;
            float4 v = make_float4(0.f, 0.f, 0.f, 0.f);
            if (row < N) {
                float4 xv = ((const float4*)x)[(size_t)row * 16 + c4];
                float4 av = ((const float4*)g_agg)[(size_t)row * 16 + c4];
                v.x = fmaf(eps1, xv.x, av.x);
                v.y = fmaf(eps1, xv.y, av.y);
                v.z = fmaf(eps1, xv.z, av.z);
                v.w = fmaf(eps1, xv.w, av.w);
            }
            __half2* dsty = (__half2*)&As[rr][c4 * 4];
            dsty[0] = __floats2half2_rn(v.x, v.y);
            dsty[1] = __floats2half2_rn(v.z, v.w);
        }
        __syncthreads();

        // ---- GEMM1 ----
        {
            wmma::fragment<wmma::accumulator, 16, 16, 16, float> acc[4];
#pragma unroll
            for (int n = 0; n < 4; n++) wmma::fill_fragment(acc[n], 0.0f);
#pragma unroll
            for (int k = 0; k < 4; k++) {
                wmma::fragment<wmma::matrix_a, 16, 16, 16, __half, wmma::row_major> af;
                wmma::load_matrix_sync(af, &As[warp * 16][k * 16], 72);
#pragma unroll
                for (int n = 0; n < 4; n++) {
                    wmma::fragment<wmma::matrix_b, 16, 16, 16, __half, wmma::row_major> bf;
                    wmma::load_matrix_sync(bf, &W1s[k * 16][n * 16], 72);
                    wmma::mma_sync(acc[n], af, bf, acc[n]);
                }
            }
            // epilogue: gelu -> back into own As strip (fp16)
#pragma unroll
            for (int n = 0; n < 4; n++) {
                wmma::store_matrix_sync(&Cs[warp][0][0], acc[n], 16, wmma::mem_row_major);
                __syncwarp();
                int r_in = lane >> 1;
                int hsel = lane & 1;
                const float* csrc = &Cs[warp][r_in][hsel * 8];
                __half tmp[8];
#pragma unroll
                for (int j = 0; j < 8; j++)
                    tmp[j] = __float2half_rn(gelu_exact(csrc[j] + bias1[n][j]));
                *(uint4*)(&As[warp * 16 + r_in][n * 16 + hsel * 8]) = *(uint4*)tmp;
                __syncwarp();
            }
        }

        // ---- GEMM2 (reads own As strip = h1) ----
        {
            wmma::fragment<wmma::accumulator, 16, 16, 16, float> acc[4];
#pragma unroll
            for (int n = 0; n < 4; n++) wmma::fill_fragment(acc[n], 0.0f);
#pragma unroll
            for (int k = 0; k < 4; k++) {
                wmma::fragment<wmma::matrix_a, 16, 16, 16, __half, wmma::row_major> af;
                wmma::load_matrix_sync(af, &As[warp * 16][k * 16], 72);
#pragma unroll
                for (int n = 0; n < 4; n++) {
                    wmma::fragment<wmma::matrix_b, 16, 16, 16, __half, wmma::row_major> bf;
                    wmma::load_matrix_sync(bf, &W2s[k * 16][n * 16], 72);
                    wmma::mma_sync(acc[n], af, bf, acc[n]);
                }
            }
#pragma unroll
            for (int n = 0; n < 4; n++) {
                wmma::store_matrix_sync(&Cs[warp][0][0], acc[n], 16, wmma::mem_row_major);
                __syncwarp();
                int r_in = lane >> 1;
                int hsel = lane & 1;
                int row  = base + warp * 16 + r_in;
                if (row < N) {
                    const float* csrc = &Cs[warp][r_in][hsel * 8];
                    float out[8];
#pragma unroll
                    for (int j = 0; j < 8; j++) out[j] = csrc[j] + bias2[n][j];
                    float* dstp = &g_h[(size_t)row * DD + n * 16 + hsel * 8];
                    *(float4*)(dstp)     = *(float4*)(out);
                    *(float4*)(dstp + 4) = *(float4*)(out + 4);
                }
                __syncwarp();
            }
        }
        __syncthreads();
    }
}

// ============================================================
// K_stat: column sums / sumsq of g_h -> BN stats
// 256 thr: thread (rg=tid>>6, d=tid&63) strides rows by 4*grid.
// ============================================================
__global__ void __launch_bounds__(256) k_stat(int layer, int N)
{
    __shared__ float sS[DD], sQ[DD];
    int tid = threadIdx.x;
    if (tid < DD) { sS[tid] = 0.f; sQ[tid] = 0.f; }
    __syncthreads();

    int d  = tid & 63;
    int rg = tid >> 6;
    float s = 0.f, q = 0.f;
    for (int row = blockIdx.x * 4 + rg; row < N; row += gridDim.x * 4) {
        float v = g_h[(size_t)row * DD + d];
        s += v;
        q = fmaf(v, v, q);
    }
    atomicAdd(&sS[d], s);
    atomicAdd(&sQ[d], q);
    __syncthreads();
    if (tid < DD) {
        atomicAdd(&g_bsum[layer][tid], sS[tid]);
        atomicAdd(&g_bsq[layer][tid],  sQ[tid]);
    }
}

// ============================================================
// K_bn: x_next = (x + gelu(BN(h))) * INV_SQRT2 ; zero agg for next layer
// ============================================================
__global__ void k_bn(int xsel, const float* __restrict__ xext,
                     int osel, float* __restrict__ oext,
                     const float* __restrict__ gamma,
                     const float* __restrict__ beta, int layer, int N)
{
    int idx = blockIdx.x * blockDim.x + threadIdx.x;
    if (idx >= N * 16) return;
    const float* xin = sel_in(xsel, xext);
    float* xout = sel_out(osel, oext);

    int q = idx & 15;
    float invN = 1.0f / (float)N;
    float4 hv = ((const float4*)g_h)[idx];
    float4 xv = ((const float4*)xin)[idx];
    float hvv[4] = {hv.x, hv.y, hv.z, hv.w};
    float xvv[4] = {xv.x, xv.y, xv.z, xv.w};
    float o[4];
#pragma unroll
    for (int j = 0; j < 4; j++) {
        int dd = q * 4 + j;
        float mu   = g_bsum[layer][dd] * invN;
        float var  = g_bsq[layer][dd] * invN - mu * mu;
        float rstd = rsqrtf(var + 1e-5f);
        float hn   = (hvv[j] - mu) * rstd * gamma[dd] + beta[dd];
        o[j] = (xvv[j] + gelu_exact(hn)) * INV_SQRT2;
    }
    ((float4*)xout)[idx] = make_float4(o[0], o[1], o[2], o[3]);
    ((float4*)g_agg)[idx] = make_float4(0.f, 0.f, 0.f, 0.f);
}

// ============================================================
// launcher
// ============================================================
extern "C" void kernel_launch(void* const* d_in, const int* in_sizes, int n_in,
                              void* d_out, int out_size)
{
    const float* x0    = (const float*)d_in[0];
    const int*   eidx  = (const int*)  d_in[1];
    const float* eattr = (const float*)d_in[2];
    const float* Wbe   = (const float*)d_in[3];
    const float* bbe   = (const float*)d_in[4];
    const float* epsp  = (const float*)d_in[5];
    const float* W1    = (const float*)d_in[6];
    const float* b1    = (const float*)d_in[7];
    const float* W2    = (const float*)d_in[8];
    const float* b2    = (const float*)d_in[9];
    const float* gamma = (const float*)d_in[10];
    const float* beta  = (const float*)d_in[11];

    int N = in_sizes[0] / DD;
    int E = in_sizes[1] / 2;
    const int* src = eidx;
    const int* dst = eidx + E;

    k_zero<<<(N * 16 + 255) / 256, 256>>>(N);
    k_bond<<<(E + 127) / 128, 256>>>(eattr, Wbe, bbe, E);

    int in_sel[3]  = {0, 1, 2};
    int out_sel[3] = {1, 2, 0};

    int nblk_node = (N * 16 + 255) / 256;
    int nblk_edge = (E * 8 + 255) / 256;
    int nblk_mlp  = (N + 127) / 128;

    for (int l = 0; l < 3; l++) {
        const float* xext = (l == 0) ? x0 : nullptr;
        k_msg <<<nblk_edge, 256>>>(in_sel[l], xext, src, dst, E);
        k_mlp <<<nblk_mlp, 256>>>(in_sel[l], xext,
                                  W1 + (size_t)l * DD * DD, b1 + (size_t)l * DD,
                                  W2 + (size_t)l * DD * DD, b2 + (size_t)l * DD,
                                  epsp, l, N);
        k_stat<<<592, 256>>>(l, N);
        k_bn  <<<nblk_node, 256>>>(in_sel[l], xext, out_sel[l], (float*)d_out,
                                   gamma + (size_t)l * DD, beta + (size_t)l * DD, l, N);
    }
}